// round 1
// baseline (speedup 1.0000x reference)
#include <cuda_runtime.h>
#include <math.h>

#define NMAX 100352
#define HID  32
#define BN_EPS 1e-3f

// Scratch (no allocations allowed in kernel_launch)
__device__ float  g_emb [NMAX * HID];  // pre-BN emb, then BN'd in place
__device__ float  g_u   [NMAX * HID];  // dst-side precompute
__device__ float  g_v   [NMAX * HID];  // src-side precompute; reused as agg
__device__ float  g_max [NMAX * HID];  // segment max buffer
__device__ double g_sums[128];         // [0:32) sum1, [32:64) sq1, [64:96) sum2, [96:128) sq2

__device__ __forceinline__ float eluf(float x) { return x > 0.f ? x : expm1f(x); }

__global__ void k_zero() {
    if (threadIdx.x < 128) g_sums[threadIdx.x] = 0.0;
}

// ---------------- K1: node encoder + BN1 stats ----------------
__global__ void k_encode(const float* __restrict__ x_cont, const int* __restrict__ x_cat,
                         const float* __restrict__ datanorm,
                         const float* __restrict__ W_cont, const float* __restrict__ b_cont,
                         const float* __restrict__ emb_charge, const float* __restrict__ emb_pdg,
                         const float* __restrict__ W_cat, const float* __restrict__ b_cat,
                         const float* __restrict__ W_enc, const float* __restrict__ b_enc,
                         int N)
{
    __shared__ float sdn[6], sWc[96], sbc[16], sch[24], spd[56], sWk[256], sbk[16], sWe[1024], sbe[32];
    __shared__ double sS[64];
    int t = threadIdx.x;
    if (t < 6)  sdn[t] = datanorm[t];
    for (int i = t; i < 96;   i += blockDim.x) sWc[i] = W_cont[i];
    if (t < 16) sbc[t] = b_cont[t];
    if (t < 24) sch[t] = emb_charge[t];
    if (t < 56) spd[t] = emb_pdg[t];
    for (int i = t; i < 256;  i += blockDim.x) sWk[i] = W_cat[i];
    if (t < 16) sbk[t] = b_cat[t];
    for (int i = t; i < 1024; i += blockDim.x) sWe[i] = W_enc[i];
    if (t < 32) sbe[t] = b_enc[t];
    if (t < 64) sS[t] = 0.0;
    __syncthreads();

    int n = blockIdx.x * blockDim.x + t;
    float h[32];
    if (n < N) {
        float in[32];
        // continuous branch -> in[16..31]
        float xc[6];
        #pragma unroll
        for (int j = 0; j < 6; j++) xc[j] = x_cont[n * 6 + j] * sdn[j];
        #pragma unroll
        for (int k = 0; k < 16; k++) {
            float a = sbc[k];
            #pragma unroll
            for (int j = 0; j < 6; j++) a += xc[j] * sWc[j * 16 + k];
            in[16 + k] = eluf(a);
        }
        // categorical branch -> in[0..15]
        int p  = x_cat[2 * n];
        int ch = x_cat[2 * n + 1];
        if (p < 0) p = -p;
        int pi = (p == 1) ? 0 : (p == 2) ? 1 : (p == 11) ? 2 : (p == 13) ? 3
               : (p == 22) ? 4 : (p == 130) ? 5 : 6;
        float c0[16];
        #pragma unroll
        for (int j = 0; j < 8; j++) {
            c0[j]     = sch[(ch + 1) * 8 + j];
            c0[8 + j] = spd[pi * 8 + j];
        }
        #pragma unroll
        for (int k = 0; k < 16; k++) {
            float a = sbk[k];
            #pragma unroll
            for (int j = 0; j < 16; j++) a += c0[j] * sWk[j * 16 + k];
            in[k] = eluf(a);
        }
        // encoder 32x32
        #pragma unroll
        for (int k = 0; k < 32; k++) {
            float a = sbe[k];
            #pragma unroll
            for (int j = 0; j < 32; j++) a += in[j] * sWe[j * 32 + k];
            h[k] = eluf(a);
            g_emb[n * 32 + k] = h[k];
        }
    } else {
        #pragma unroll
        for (int k = 0; k < 32; k++) h[k] = 0.f;
    }

    // BN1 stats: warp butterfly per feature, lane k owns feature k
    int lane = t & 31;
    #pragma unroll
    for (int k = 0; k < 32; k++) {
        float s = h[k];
        float q = h[k] * h[k];
        #pragma unroll
        for (int off = 16; off; off >>= 1) {
            s += __shfl_xor_sync(0xffffffffu, s, off);
            q += __shfl_xor_sync(0xffffffffu, q, off);
        }
        if (lane == k) {
            atomicAdd(&sS[k],      (double)s);
            atomicAdd(&sS[32 + k], (double)q);
        }
    }
    __syncthreads();
    if (t < 64) atomicAdd(&g_sums[t], sS[t]);
}

// ---------------- K2: apply BN1, compute u,v, init maxbuf ----------------
__global__ void k_prep(const float* __restrict__ g_all, const float* __restrict__ be_all,
                       const float* __restrict__ W_msg, int N)
{
    __shared__ float sWd[1024], sWb[1024], sScale[32], sShift[32];
    int t = threadIdx.x;
    for (int i = t; i < 1024; i += blockDim.x) {
        float a = W_msg[i];
        float b = W_msg[1024 + i];
        sWd[i] = a - b;
        sWb[i] = b;
    }
    if (t < 32) {
        double m   = g_sums[t] / (double)N;
        double var = g_sums[32 + t] / (double)N - m * m;
        float inv  = rsqrtf((float)var + BN_EPS);
        sScale[t]  = g_all[t] * inv;
        sShift[t]  = be_all[t] - (float)m * g_all[t] * inv;
    }
    __syncthreads();

    int n = blockIdx.x * blockDim.x + t;
    if (n >= N) return;
    float e[32];
    #pragma unroll
    for (int k = 0; k < 32; k++) {
        float x = g_emb[n * 32 + k] * sScale[k] + sShift[k];
        e[k] = x;
        g_emb[n * 32 + k] = x;
    }
    const float ninf = __int_as_float(0xff800000);
    #pragma unroll
    for (int k = 0; k < 32; k++) {
        float au = 0.f, av = 0.f;
        #pragma unroll
        for (int j = 0; j < 32; j++) {
            au += e[j] * sWd[j * 32 + k];
            av += e[j] * sWb[j * 32 + k];
        }
        g_u[n * 32 + k]   = au;
        g_v[n * 32 + k]   = av;
        g_max[n * 32 + k] = ninf;
    }
}

// ---------------- K3: edge atomic max ----------------
__global__ void k_edge(const int* __restrict__ ei, int E)
{
    long long gid = (long long)blockIdx.x * blockDim.x + threadIdx.x;
    int e = (int)(gid >> 5);
    int lane = (int)(gid & 31);
    if (e >= E) return;
    int s = __ldg(&ei[e]);
    int d = __ldg(&ei[E + e]);
    float val = __ldg(&g_v[(long long)s * 32 + lane]);
    float* addr = &g_max[(long long)d * 32 + lane];
    float cur = *addr;  // buffer is monotone non-decreasing -> stale read only causes a redundant atomic
    if (val > cur) {
        if (__float_as_int(val) >= 0) atomicMax((int*)addr, __float_as_int(val));
        else                          atomicMin((unsigned int*)addr, __float_as_uint(val));
    }
}

// ---------------- K4: finalize agg + BN2 stats ----------------
__global__ void k_agg(const float* __restrict__ b_msg, int N)
{
    __shared__ float sb[32];
    __shared__ double sS[64];
    int t = threadIdx.x;
    if (t < 32) sb[t] = b_msg[t];
    if (t < 64) sS[t] = 0.0;
    __syncthreads();

    int n = blockIdx.x * blockDim.x + t;
    float a[32];
    if (n < N) {
        float m0 = g_max[n * 32];
        bool empty = (__float_as_int(m0) == (int)0xff800000);
        #pragma unroll
        for (int k = 0; k < 32; k++) {
            float x = empty ? 0.f : (g_u[n * 32 + k] + sb[k] + g_max[n * 32 + k]);
            a[k] = x;
            g_v[n * 32 + k] = x;  // reuse g_v as agg
        }
    } else {
        #pragma unroll
        for (int k = 0; k < 32; k++) a[k] = 0.f;
    }

    int lane = t & 31;
    #pragma unroll
    for (int k = 0; k < 32; k++) {
        float s = a[k];
        float q = a[k] * a[k];
        #pragma unroll
        for (int off = 16; off; off >>= 1) {
            s += __shfl_xor_sync(0xffffffffu, s, off);
            q += __shfl_xor_sync(0xffffffffu, q, off);
        }
        if (lane == k) {
            atomicAdd(&sS[k],      (double)s);
            atomicAdd(&sS[32 + k], (double)q);
        }
    }
    __syncthreads();
    if (t < 64) atomicAdd(&g_sums[64 + t], sS[t]);
}

// ---------------- K5: residual + output MLP ----------------
__global__ void k_out(const float* __restrict__ g_conv, const float* __restrict__ be_conv,
                      const float* __restrict__ W_o1, const float* __restrict__ b_o1,
                      const float* __restrict__ W_o2, const float* __restrict__ b_o2,
                      float* __restrict__ out, int N)
{
    __shared__ float sW1[512], sb1[16], sW2[16], sScale[32], sShift[32], sb2;
    int t = threadIdx.x;
    for (int i = t; i < 512; i += blockDim.x) sW1[i] = W_o1[i];
    if (t < 16) sb1[t] = b_o1[t];
    if (t < 16) sW2[t] = W_o2[t];
    if (t == 0) sb2 = b_o2[0];
    if (t < 32) {
        double m   = g_sums[64 + t] / (double)N;
        double var = g_sums[96 + t] / (double)N - m * m;
        float inv  = rsqrtf((float)var + BN_EPS);
        sScale[t]  = g_conv[t] * inv;
        sShift[t]  = be_conv[t] - (float)m * g_conv[t] * inv;
    }
    __syncthreads();

    int n = blockIdx.x * blockDim.x + t;
    if (n >= N) return;
    float h[32];
    #pragma unroll
    for (int k = 0; k < 32; k++)
        h[k] = g_emb[n * 32 + k] + g_v[n * 32 + k] * sScale[k] + sShift[k];
    float o1[16];
    #pragma unroll
    for (int k = 0; k < 16; k++) {
        float a = sb1[k];
        #pragma unroll
        for (int j = 0; j < 32; j++) a += h[j] * sW1[j * 16 + k];
        o1[k] = eluf(a);
    }
    float r = sb2;
    #pragma unroll
    for (int j = 0; j < 16; j++) r += o1[j] * sW2[j];
    out[n] = r;
}

extern "C" void kernel_launch(void* const* d_in, const int* in_sizes, int n_in,
                              void* d_out, int out_size)
{
    const float* x_cont     = (const float*)d_in[0];
    const int*   x_cat      = (const int*)  d_in[1];
    const int*   edge_index = (const int*)  d_in[2];
    // d_in[3] = batch (unused)
    const float* datanorm   = (const float*)d_in[4];
    const float* W_cont     = (const float*)d_in[5];
    const float* b_cont     = (const float*)d_in[6];
    const float* emb_charge = (const float*)d_in[7];
    const float* emb_pdg    = (const float*)d_in[8];
    const float* W_cat      = (const float*)d_in[9];
    const float* b_cat      = (const float*)d_in[10];
    const float* W_enc      = (const float*)d_in[11];
    const float* b_enc      = (const float*)d_in[12];
    const float* g_all      = (const float*)d_in[13];
    const float* be_all     = (const float*)d_in[14];
    const float* W_msg      = (const float*)d_in[15];
    const float* b_msg      = (const float*)d_in[16];
    const float* g_conv     = (const float*)d_in[17];
    const float* be_conv    = (const float*)d_in[18];
    const float* W_o1       = (const float*)d_in[19];
    const float* b_o1       = (const float*)d_in[20];
    const float* W_o2       = (const float*)d_in[21];
    const float* b_o2       = (const float*)d_in[22];
    float* out = (float*)d_out;

    int N = in_sizes[0] / 6;
    int E = in_sizes[2] / 2;

    int nb = (N + 255) / 256;
    k_zero<<<1, 128>>>();
    k_encode<<<nb, 256>>>(x_cont, x_cat, datanorm, W_cont, b_cont,
                          emb_charge, emb_pdg, W_cat, b_cat, W_enc, b_enc, N);
    k_prep<<<nb, 256>>>(g_all, be_all, W_msg, N);
    long long tot = (long long)E * 32;
    int eb = (int)((tot + 255) / 256);
    k_edge<<<eb, 256>>>(edge_index, E);
    k_agg<<<nb, 256>>>(b_msg, N);
    k_out<<<nb, 256>>>(g_conv, be_conv, W_o1, b_o1, W_o2, b_o2, out, N);
}

// round 2
// speedup vs baseline: 1.2884x; 1.2884x over previous
#include <cuda_runtime.h>
#include <math.h>

#define NMAX 100352
#define HID  32
#define BN_EPS 1e-3f

// Scratch (no allocations allowed in kernel_launch)
__device__ float  g_emb [NMAX * HID];  // pre-BN emb, then BN'd in place
__device__ float  g_u   [NMAX * HID];  // dst-side precompute
__device__ float  g_v   [NMAX * HID];  // src-side precompute; reused as agg
__device__ float  g_max [NMAX * HID];  // segment max buffer
__device__ double g_sums[128];         // [0:32) sum1, [32:64) sq1, [64:96) sum2, [96:128) sq2

__device__ __forceinline__ float eluf(float x) { return x > 0.f ? x : expm1f(x); }

__global__ void k_zero() {
    if (threadIdx.x < 128) g_sums[threadIdx.x] = 0.0;
}

// ---------------- K1: node encoder + BN1 stats + maxbuf init ----------------
__global__ void k_encode(const float* __restrict__ x_cont, const int* __restrict__ x_cat,
                         const float* __restrict__ datanorm,
                         const float* __restrict__ W_cont, const float* __restrict__ b_cont,
                         const float* __restrict__ emb_charge, const float* __restrict__ emb_pdg,
                         const float* __restrict__ W_cat, const float* __restrict__ b_cat,
                         const float* __restrict__ W_enc, const float* __restrict__ b_enc,
                         int N)
{
    __shared__ float sdn[6], sWc[96], sbc[16], sch[24], spd[56], sWk[256], sbk[16], sWe[1024], sbe[32];
    __shared__ double sS[64];
    int t = threadIdx.x;
    if (t < 6)  sdn[t] = datanorm[t];
    for (int i = t; i < 96;   i += blockDim.x) sWc[i] = W_cont[i];
    if (t < 16) sbc[t] = b_cont[t];
    if (t < 24) sch[t] = emb_charge[t];
    if (t < 56) spd[t] = emb_pdg[t];
    for (int i = t; i < 256;  i += blockDim.x) sWk[i] = W_cat[i];
    if (t < 16) sbk[t] = b_cat[t];
    for (int i = t; i < 1024; i += blockDim.x) sWe[i] = W_enc[i];
    if (t < 32) sbe[t] = b_enc[t];
    if (t < 64) sS[t] = 0.0;
    __syncthreads();

    int n = blockIdx.x * blockDim.x + t;
    float h[32];
    if (n < N) {
        float in[32];
        // continuous branch -> in[16..31]
        float xc[6];
        #pragma unroll
        for (int j = 0; j < 6; j++) xc[j] = x_cont[n * 6 + j] * sdn[j];
        #pragma unroll
        for (int k = 0; k < 16; k++) {
            float a = sbc[k];
            #pragma unroll
            for (int j = 0; j < 6; j++) a += xc[j] * sWc[j * 16 + k];
            in[16 + k] = eluf(a);
        }
        // categorical branch -> in[0..15]
        int p  = x_cat[2 * n];
        int ch = x_cat[2 * n + 1];
        if (p < 0) p = -p;
        int pi = (p == 1) ? 0 : (p == 2) ? 1 : (p == 11) ? 2 : (p == 13) ? 3
               : (p == 22) ? 4 : (p == 130) ? 5 : 6;
        float c0[16];
        #pragma unroll
        for (int j = 0; j < 8; j++) {
            c0[j]     = sch[(ch + 1) * 8 + j];
            c0[8 + j] = spd[pi * 8 + j];
        }
        #pragma unroll
        for (int k = 0; k < 16; k++) {
            float a = sbk[k];
            #pragma unroll
            for (int j = 0; j < 16; j++) a += c0[j] * sWk[j * 16 + k];
            in[k] = eluf(a);
        }
        // encoder 32x32
        const float ninf = __int_as_float(0xff800000);
        #pragma unroll
        for (int k = 0; k < 32; k++) {
            float a = sbe[k];
            #pragma unroll
            for (int j = 0; j < 32; j++) a += in[j] * sWe[j * 32 + k];
            h[k] = eluf(a);
            g_emb[n * 32 + k] = h[k];
            g_max[n * 32 + k] = ninf;
        }
    } else {
        #pragma unroll
        for (int k = 0; k < 32; k++) h[k] = 0.f;
    }

    // BN1 stats: warp butterfly per feature, lane k owns feature k
    int lane = t & 31;
    #pragma unroll
    for (int k = 0; k < 32; k++) {
        float s = h[k];
        float q = h[k] * h[k];
        #pragma unroll
        for (int off = 16; off; off >>= 1) {
            s += __shfl_xor_sync(0xffffffffu, s, off);
            q += __shfl_xor_sync(0xffffffffu, q, off);
        }
        if (lane == k) {
            atomicAdd(&sS[k],      (double)s);
            atomicAdd(&sS[32 + k], (double)q);
        }
    }
    __syncthreads();
    if (t < 64) atomicAdd(&g_sums[t], sS[t]);
}

// ---------------- K2: apply BN1, compute u,v ----------------
__global__ void k_prep(const float* __restrict__ g_all, const float* __restrict__ be_all,
                       const float* __restrict__ W_msg, int N)
{
    __shared__ float2 sW[1024];            // (W_top - W_bot, W_bot)
    __shared__ float  sScale[32], sShift[32];
    int t = threadIdx.x;
    for (int i = t; i < 1024; i += blockDim.x) {
        float a = W_msg[i];
        float b = W_msg[1024 + i];
        sW[i] = make_float2(a - b, b);
    }
    if (t < 32) {
        double m   = g_sums[t] / (double)N;
        double var = g_sums[32 + t] / (double)N - m * m;
        float inv  = rsqrtf((float)var + BN_EPS);
        sScale[t]  = g_all[t] * inv;
        sShift[t]  = be_all[t] - (float)m * g_all[t] * inv;
    }
    __syncthreads();

    int n = blockIdx.x * blockDim.x + t;
    if (n >= N) return;
    float e[32];
    #pragma unroll
    for (int k = 0; k < 32; k++) {
        float x = g_emb[n * 32 + k] * sScale[k] + sShift[k];
        e[k] = x;
        g_emb[n * 32 + k] = x;
    }
    #pragma unroll
    for (int k = 0; k < 32; k++) {
        float au = 0.f, av = 0.f;
        #pragma unroll
        for (int j = 0; j < 32; j++) {
            float2 w = sW[j * 32 + k];
            au += e[j] * w.x;
            av += e[j] * w.y;
        }
        g_u[n * 32 + k] = au;
        g_v[n * 32 + k] = av;
    }
}

// ---------------- K3: edge atomic max (float4, 2 edges/thread) ----------------
__device__ __forceinline__ void amax1(float* a, float v, float c) {
    if (v > c) {
        if (__float_as_int(v) >= 0) atomicMax((int*)a, __float_as_int(v));
        else                        atomicMin((unsigned int*)a, __float_as_uint(v));
    }
}

__global__ void k_edge(const int* __restrict__ ei, int E, int EH)
{
    int tid = blockIdx.x * blockDim.x + threadIdx.x;
    int c = tid & 7;                 // float4 chunk within feature row
    int e0 = tid >> 3;               // first edge
    if (e0 >= EH) return;
    int e1 = e0 + EH;
    bool has1 = (e1 < E);

    // batch index loads (MLP)
    int s0 = __ldg(&ei[e0]);
    int d0 = __ldg(&ei[E + e0]);
    int s1 = has1 ? __ldg(&ei[e1])     : s0;
    int d1 = has1 ? __ldg(&ei[E + e1]) : d0;

    const float4* v4 = (const float4*)g_v;
    float4* m4 = (float4*)g_max;

    float4 val0 = __ldg(&v4[(long long)s0 * 8 + c]);
    float4 val1 = __ldg(&v4[(long long)s1 * 8 + c]);
    // monotone buffer: stale pre-read only causes a redundant atomic, never a miss
    float4 cur0 = m4[(long long)d0 * 8 + c];
    float4 cur1 = m4[(long long)d1 * 8 + c];

    float* a0 = &g_max[(long long)d0 * 32 + c * 4];
    amax1(a0 + 0, val0.x, cur0.x);
    amax1(a0 + 1, val0.y, cur0.y);
    amax1(a0 + 2, val0.z, cur0.z);
    amax1(a0 + 3, val0.w, cur0.w);
    if (has1) {
        float* a1 = &g_max[(long long)d1 * 32 + c * 4];
        amax1(a1 + 0, val1.x, cur1.x);
        amax1(a1 + 1, val1.y, cur1.y);
        amax1(a1 + 2, val1.z, cur1.z);
        amax1(a1 + 3, val1.w, cur1.w);
    }
}

// ---------------- K4: finalize agg + BN2 stats ----------------
__global__ void k_agg(const float* __restrict__ b_msg, int N)
{
    __shared__ float sb[32];
    __shared__ double sS[64];
    int t = threadIdx.x;
    if (t < 32) sb[t] = b_msg[t];
    if (t < 64) sS[t] = 0.0;
    __syncthreads();

    int n = blockIdx.x * blockDim.x + t;
    float a[32];
    if (n < N) {
        float m0 = g_max[n * 32];
        bool empty = (__float_as_int(m0) == (int)0xff800000);
        #pragma unroll
        for (int k = 0; k < 32; k++) {
            float x = empty ? 0.f : (g_u[n * 32 + k] + sb[k] + g_max[n * 32 + k]);
            a[k] = x;
            g_v[n * 32 + k] = x;  // reuse g_v as agg
        }
    } else {
        #pragma unroll
        for (int k = 0; k < 32; k++) a[k] = 0.f;
    }

    int lane = t & 31;
    #pragma unroll
    for (int k = 0; k < 32; k++) {
        float s = a[k];
        float q = a[k] * a[k];
        #pragma unroll
        for (int off = 16; off; off >>= 1) {
            s += __shfl_xor_sync(0xffffffffu, s, off);
            q += __shfl_xor_sync(0xffffffffu, q, off);
        }
        if (lane == k) {
            atomicAdd(&sS[k],      (double)s);
            atomicAdd(&sS[32 + k], (double)q);
        }
    }
    __syncthreads();
    if (t < 64) atomicAdd(&g_sums[64 + t], sS[t]);
}

// ---------------- K5: residual + output MLP ----------------
__global__ void k_out(const float* __restrict__ g_conv, const float* __restrict__ be_conv,
                      const float* __restrict__ W_o1, const float* __restrict__ b_o1,
                      const float* __restrict__ W_o2, const float* __restrict__ b_o2,
                      float* __restrict__ out, int N)
{
    __shared__ float sW1[512], sb1[16], sW2[16], sScale[32], sShift[32], sb2;
    int t = threadIdx.x;
    for (int i = t; i < 512; i += blockDim.x) sW1[i] = W_o1[i];
    if (t < 16) sb1[t] = b_o1[t];
    if (t < 16) sW2[t] = W_o2[t];
    if (t == 0) sb2 = b_o2[0];
    if (t < 32) {
        double m   = g_sums[64 + t] / (double)N;
        double var = g_sums[96 + t] / (double)N - m * m;
        float inv  = rsqrtf((float)var + BN_EPS);
        sScale[t]  = g_conv[t] * inv;
        sShift[t]  = be_conv[t] - (float)m * g_conv[t] * inv;
    }
    __syncthreads();

    int n = blockIdx.x * blockDim.x + t;
    if (n >= N) return;
    float h[32];
    #pragma unroll
    for (int k = 0; k < 32; k++)
        h[k] = g_emb[n * 32 + k] + g_v[n * 32 + k] * sScale[k] + sShift[k];
    float o1[16];
    #pragma unroll
    for (int k = 0; k < 16; k++) {
        float a = sb1[k];
        #pragma unroll
        for (int j = 0; j < 32; j++) a += h[j] * sW1[j * 16 + k];
        o1[k] = eluf(a);
    }
    float r = sb2;
    #pragma unroll
    for (int j = 0; j < 16; j++) r += o1[j] * sW2[j];
    out[n] = r;
}

extern "C" void kernel_launch(void* const* d_in, const int* in_sizes, int n_in,
                              void* d_out, int out_size)
{
    const float* x_cont     = (const float*)d_in[0];
    const int*   x_cat      = (const int*)  d_in[1];
    const int*   edge_index = (const int*)  d_in[2];
    // d_in[3] = batch (unused)
    const float* datanorm   = (const float*)d_in[4];
    const float* W_cont     = (const float*)d_in[5];
    const float* b_cont     = (const float*)d_in[6];
    const float* emb_charge = (const float*)d_in[7];
    const float* emb_pdg    = (const float*)d_in[8];
    const float* W_cat      = (const float*)d_in[9];
    const float* b_cat      = (const float*)d_in[10];
    const float* W_enc      = (const float*)d_in[11];
    const float* b_enc      = (const float*)d_in[12];
    const float* g_all      = (const float*)d_in[13];
    const float* be_all     = (const float*)d_in[14];
    const float* W_msg      = (const float*)d_in[15];
    const float* b_msg      = (const float*)d_in[16];
    const float* g_conv     = (const float*)d_in[17];
    const float* be_conv    = (const float*)d_in[18];
    const float* W_o1       = (const float*)d_in[19];
    const float* b_o1       = (const float*)d_in[20];
    const float* W_o2       = (const float*)d_in[21];
    const float* b_o2       = (const float*)d_in[22];
    float* out = (float*)d_out;

    int N = in_sizes[0] / 6;
    int E = in_sizes[2] / 2;

    int nb = (N + 255) / 256;
    k_zero<<<1, 128>>>();
    k_encode<<<nb, 256>>>(x_cont, x_cat, datanorm, W_cont, b_cont,
                          emb_charge, emb_pdg, W_cat, b_cat, W_enc, b_enc, N);
    k_prep<<<nb, 256>>>(g_all, be_all, W_msg, N);
    int EH = (E + 1) / 2;
    long long tot = (long long)EH * 8;
    int eb = (int)((tot + 255) / 256);
    k_edge<<<eb, 256>>>(edge_index, E, EH);
    k_agg<<<nb, 256>>>(b_msg, N);
    k_out<<<nb, 256>>>(g_conv, be_conv, W_o1, b_o1, W_o2, b_o2, out, N);
}

// round 3
// speedup vs baseline: 1.5926x; 1.2361x over previous
#include <cuda_runtime.h>
#include <math.h>

#define NMAX 100352
#define HID  32
#define BN_EPS 1e-3f

__device__ float  g_emb [NMAX * HID];
__device__ float  g_u   [NMAX * HID];
__device__ float  g_v   [NMAX * HID];   // src-side precompute; reused as agg
__device__ float  g_max [NMAX * HID];
__device__ double g_sums[128];          // [0:32) sum1, [32:64) sq1, [64:96) sum2, [96:128) sq2

__device__ __forceinline__ float eluf(float x) { return x > 0.f ? x : expm1f(x); }

__global__ void k_zero() {
    if (threadIdx.x < 128) g_sums[threadIdx.x] = 0.0;
}

// ---------------- K1: node encoder + BN1 stats + maxbuf init (warp/node, lane=feature) ----
__global__ void k_encode(const float* __restrict__ x_cont, const int* __restrict__ x_cat,
                         const float* __restrict__ datanorm,
                         const float* __restrict__ W_cont, const float* __restrict__ b_cont,
                         const float* __restrict__ emb_charge, const float* __restrict__ emb_pdg,
                         const float* __restrict__ W_cat, const float* __restrict__ b_cat,
                         const float* __restrict__ W_enc, const float* __restrict__ b_enc,
                         int N)
{
    int lane = threadIdx.x & 31;
    int gw   = (blockIdx.x * blockDim.x + threadIdx.x) >> 5;
    int nw   = (gridDim.x * blockDim.x) >> 5;
    int l16  = lane & 15;

    // weight-stationary columns in registers
    float wcat[16], wcont[6], wenc[32];
    #pragma unroll
    for (int j = 0; j < 16; j++) wcat[j] = W_cat[j * 16 + l16];
    #pragma unroll
    for (int j = 0; j < 6; j++)  wcont[j] = W_cont[j * 16 + l16];
    #pragma unroll
    for (int j = 0; j < 32; j++) wenc[j] = W_enc[j * 32 + lane];
    float bcat  = b_cat[l16];
    float bcont = b_cont[l16];
    float benc  = b_enc[lane];
    float dnr   = (lane < 6) ? datanorm[lane] : 0.f;

    const float ninf = __int_as_float(0xff800000);
    float accs = 0.f, accq = 0.f;

    for (int n = gw; n < N; n += nw) {
        int2 cat = __ldg((const int2*)x_cat + n);
        int p = cat.x < 0 ? -cat.x : cat.x;
        int pi = (p == 1) ? 0 : (p == 2) ? 1 : (p == 11) ? 2 : (p == 13) ? 3
               : (p == 22) ? 4 : (p == 130) ? 5 : 6;

        float xi = (lane < 6) ? x_cont[n * 6 + lane] * dnr : 0.f;
        float c0 = (lane < 8)  ? emb_charge[(cat.y + 1) * 8 + lane]
                 : (lane < 16) ? emb_pdg[pi * 8 + lane - 8] : 0.f;

        float acat = bcat;
        #pragma unroll
        for (int j = 0; j < 16; j++)
            acat += __shfl_sync(0xffffffffu, c0, j) * wcat[j];
        float acont = bcont;
        #pragma unroll
        for (int j = 0; j < 6; j++)
            acont += __shfl_sync(0xffffffffu, xi, j) * wcont[j];

        float in = eluf(lane < 16 ? acat : acont);

        float a = benc;
        #pragma unroll
        for (int j = 0; j < 32; j++)
            a += __shfl_sync(0xffffffffu, in, j) * wenc[j];
        float h = eluf(a);

        g_emb[(long long)n * 32 + lane] = h;
        g_max[(long long)n * 32 + lane] = ninf;
        accs += h;
        accq += h * h;
    }
    atomicAdd(&g_sums[lane],      (double)accs);
    atomicAdd(&g_sums[32 + lane], (double)accq);
}

// ---------------- K2: apply BN1, compute u,v (warp/node) ----------------
__global__ void k_prep(const float* __restrict__ g_all, const float* __restrict__ be_all,
                       const float* __restrict__ W_msg, int N)
{
    int lane = threadIdx.x & 31;
    int gw   = (blockIdx.x * blockDim.x + threadIdx.x) >> 5;
    int nw   = (gridDim.x * blockDim.x) >> 5;

    float wd[32], wb[32];
    #pragma unroll
    for (int j = 0; j < 32; j++) {
        float a = W_msg[j * 32 + lane];
        float b = W_msg[1024 + j * 32 + lane];
        wd[j] = a - b;
        wb[j] = b;
    }
    double m   = g_sums[lane] / (double)N;
    double var = g_sums[32 + lane] / (double)N - m * m;
    float inv  = rsqrtf((float)var + BN_EPS);
    float ga   = g_all[lane];
    float scale = ga * inv;
    float shift = be_all[lane] - (float)m * ga * inv;

    for (int n = gw; n < N; n += nw) {
        float x = g_emb[(long long)n * 32 + lane] * scale + shift;
        g_emb[(long long)n * 32 + lane] = x;
        float au = 0.f, av = 0.f;
        #pragma unroll
        for (int j = 0; j < 32; j++) {
            float ej = __shfl_sync(0xffffffffu, x, j);
            au += ej * wd[j];
            av += ej * wb[j];
        }
        g_u[(long long)n * 32 + lane] = au;
        g_v[(long long)n * 32 + lane] = av;
    }
}

// ---------------- K3: edge atomic max (float4, 2 edges/thread) ----------------
__device__ __forceinline__ void amax1(float* a, float v, float c) {
    if (v > c) {
        if (__float_as_int(v) >= 0) atomicMax((int*)a, __float_as_int(v));
        else                        atomicMin((unsigned int*)a, __float_as_uint(v));
    }
}

__global__ void k_edge(const int* __restrict__ ei, int E, int EH)
{
    int tid = blockIdx.x * blockDim.x + threadIdx.x;
    int c = tid & 7;
    int e0 = tid >> 3;
    if (e0 >= EH) return;
    int e1 = e0 + EH;
    bool has1 = (e1 < E);

    int s0 = __ldg(&ei[e0]);
    int d0 = __ldg(&ei[E + e0]);
    int s1 = has1 ? __ldg(&ei[e1])     : s0;
    int d1 = has1 ? __ldg(&ei[E + e1]) : d0;

    const float4* v4 = (const float4*)g_v;
    float4* m4 = (float4*)g_max;

    float4 val0 = __ldg(&v4[(long long)s0 * 8 + c]);
    float4 val1 = __ldg(&v4[(long long)s1 * 8 + c]);
    float4 cur0 = m4[(long long)d0 * 8 + c];
    float4 cur1 = m4[(long long)d1 * 8 + c];

    float* a0 = &g_max[(long long)d0 * 32 + c * 4];
    amax1(a0 + 0, val0.x, cur0.x);
    amax1(a0 + 1, val0.y, cur0.y);
    amax1(a0 + 2, val0.z, cur0.z);
    amax1(a0 + 3, val0.w, cur0.w);
    if (has1) {
        float* a1 = &g_max[(long long)d1 * 32 + c * 4];
        amax1(a1 + 0, val1.x, cur1.x);
        amax1(a1 + 1, val1.y, cur1.y);
        amax1(a1 + 2, val1.z, cur1.z);
        amax1(a1 + 3, val1.w, cur1.w);
    }
}

// ---------------- K4: finalize agg + BN2 stats (warp/node) ----------------
__global__ void k_agg(const float* __restrict__ b_msg, int N)
{
    int lane = threadIdx.x & 31;
    int gw   = (blockIdx.x * blockDim.x + threadIdx.x) >> 5;
    int nw   = (gridDim.x * blockDim.x) >> 5;
    float bmr = b_msg[lane];
    float accs = 0.f, accq = 0.f;

    for (int n = gw; n < N; n += nw) {
        float mval = g_max[(long long)n * 32 + lane];
        float uval = g_u[(long long)n * 32 + lane];
        int m0 = __shfl_sync(0xffffffffu, __float_as_int(mval), 0);
        bool empty = (m0 == (int)0xff800000);
        float x = empty ? 0.f : (uval + bmr + mval);
        g_v[(long long)n * 32 + lane] = x;
        accs += x;
        accq += x * x;
    }
    atomicAdd(&g_sums[64 + lane], (double)accs);
    atomicAdd(&g_sums[96 + lane], (double)accq);
}

// ---------------- K5: residual + output MLP (warp/node) ----------------
__global__ void k_out(const float* __restrict__ g_conv, const float* __restrict__ be_conv,
                      const float* __restrict__ W_o1, const float* __restrict__ b_o1,
                      const float* __restrict__ W_o2, const float* __restrict__ b_o2,
                      float* __restrict__ out, int N)
{
    int lane = threadIdx.x & 31;
    int gw   = (blockIdx.x * blockDim.x + threadIdx.x) >> 5;
    int nw   = (gridDim.x * blockDim.x) >> 5;
    int l16  = lane & 15;

    float w1[32];
    #pragma unroll
    for (int j = 0; j < 32; j++) w1[j] = W_o1[j * 16 + l16];
    float w2 = W_o2[l16];
    float b1 = b_o1[l16];
    float b2 = b_o2[0];

    double m   = g_sums[64 + lane] / (double)N;
    double var = g_sums[96 + lane] / (double)N - m * m;
    float inv  = rsqrtf((float)var + BN_EPS);
    float gc   = g_conv[lane];
    float scale = gc * inv;
    float shift = be_conv[lane] - (float)m * gc * inv;

    for (int n = gw; n < N; n += nw) {
        float h = g_emb[(long long)n * 32 + lane]
                + g_v[(long long)n * 32 + lane] * scale + shift;
        float a = b1;
        #pragma unroll
        for (int j = 0; j < 32; j++)
            a += __shfl_sync(0xffffffffu, h, j) * w1[j];
        float o1 = eluf(a);
        float mm = o1 * w2;
        mm += __shfl_xor_sync(0xffffffffu, mm, 1);
        mm += __shfl_xor_sync(0xffffffffu, mm, 2);
        mm += __shfl_xor_sync(0xffffffffu, mm, 4);
        mm += __shfl_xor_sync(0xffffffffu, mm, 8);
        if (lane == 0) out[n] = mm + b2;
    }
}

extern "C" void kernel_launch(void* const* d_in, const int* in_sizes, int n_in,
                              void* d_out, int out_size)
{
    const float* x_cont     = (const float*)d_in[0];
    const int*   x_cat      = (const int*)  d_in[1];
    const int*   edge_index = (const int*)  d_in[2];
    const float* datanorm   = (const float*)d_in[4];
    const float* W_cont     = (const float*)d_in[5];
    const float* b_cont     = (const float*)d_in[6];
    const float* emb_charge = (const float*)d_in[7];
    const float* emb_pdg    = (const float*)d_in[8];
    const float* W_cat      = (const float*)d_in[9];
    const float* b_cat      = (const float*)d_in[10];
    const float* W_enc      = (const float*)d_in[11];
    const float* b_enc      = (const float*)d_in[12];
    const float* g_all      = (const float*)d_in[13];
    const float* be_all     = (const float*)d_in[14];
    const float* W_msg      = (const float*)d_in[15];
    const float* b_msg      = (const float*)d_in[16];
    const float* g_conv     = (const float*)d_in[17];
    const float* be_conv    = (const float*)d_in[18];
    const float* W_o1       = (const float*)d_in[19];
    const float* b_o1       = (const float*)d_in[20];
    const float* W_o2       = (const float*)d_in[21];
    const float* b_o2       = (const float*)d_in[22];
    float* out = (float*)d_out;

    int N = in_sizes[0] / 6;
    int E = in_sizes[2] / 2;

    // warp-per-node kernels: 128 threads/block, ~8k warps total (~12 nodes/warp)
    const int TB = 128;
    const int NB = 2048;

    k_zero<<<1, 128>>>();
    k_encode<<<NB, TB>>>(x_cont, x_cat, datanorm, W_cont, b_cont,
                         emb_charge, emb_pdg, W_cat, b_cat, W_enc, b_enc, N);
    k_prep<<<NB, TB>>>(g_all, be_all, W_msg, N);
    int EH = (E + 1) / 2;
    long long tot = (long long)EH * 8;
    int eb = (int)((tot + 255) / 256);
    k_edge<<<eb, 256>>>(edge_index, E, EH);
    k_agg<<<NB, TB>>>(b_msg, N);
    k_out<<<NB, TB>>>(g_conv, be_conv, W_o1, b_o1, W_o2, b_o2, out, N);
}

// round 4
// speedup vs baseline: 2.1447x; 1.3467x over previous
#include <cuda_runtime.h>
#include <math.h>

#define NMAX 100352
#define HID  32
#define BN_EPS 1e-3f

__device__ float  g_emb [NMAX * HID];
__device__ float  g_u   [NMAX * HID];
__device__ float  g_v   [NMAX * HID];   // src-side precompute; reused as agg
__device__ float  g_max [NMAX * HID];
__device__ double g_sums[128];          // [0:32) sum1, [32:64) sq1, [64:96) sum2, [96:128) sq2

__device__ __forceinline__ float eluf(float x) { return x > 0.f ? x : expm1f(x); }

__global__ void k_zero() {
    if (threadIdx.x < 128) g_sums[threadIdx.x] = 0.0;
}

// block-level stats flush: per-warp float partials -> double -> ONE atomic/feature/block
__device__ __forceinline__ void flush_stats(float accs, float accq, int sumoff) {
    __shared__ float ss[8][32], sq[8][32];
    int lane = threadIdx.x & 31;
    int w    = threadIdx.x >> 5;
    ss[w][lane] = accs;
    sq[w][lane] = accq;
    __syncthreads();
    if (threadIdx.x < 32) {
        double s = 0.0, q = 0.0;
        #pragma unroll
        for (int k = 0; k < 8; k++) { s += (double)ss[k][lane]; q += (double)sq[k][lane]; }
        atomicAdd(&g_sums[sumoff + lane],      s);
        atomicAdd(&g_sums[sumoff + 32 + lane], q);
    }
}

// ---------------- K1: node encoder + BN1 stats + maxbuf init (warp/node, lane=feature) ----
__global__ void k_encode(const float* __restrict__ x_cont, const int* __restrict__ x_cat,
                         const float* __restrict__ datanorm,
                         const float* __restrict__ W_cont, const float* __restrict__ b_cont,
                         const float* __restrict__ emb_charge, const float* __restrict__ emb_pdg,
                         const float* __restrict__ W_cat, const float* __restrict__ b_cat,
                         const float* __restrict__ W_enc, const float* __restrict__ b_enc,
                         int N)
{
    int lane = threadIdx.x & 31;
    int gw   = (blockIdx.x * blockDim.x + threadIdx.x) >> 5;
    int nw   = (gridDim.x * blockDim.x) >> 5;
    int l16  = lane & 15;

    // weight-stationary columns in registers
    float wcat[16], wcont[6], wenc[32];
    #pragma unroll
    for (int j = 0; j < 16; j++) wcat[j] = W_cat[j * 16 + l16];
    #pragma unroll
    for (int j = 0; j < 6; j++)  wcont[j] = W_cont[j * 16 + l16];
    #pragma unroll
    for (int j = 0; j < 32; j++) wenc[j] = W_enc[j * 32 + lane];
    float bcat  = b_cat[l16];
    float bcont = b_cont[l16];
    float benc  = b_enc[lane];
    float dnr   = (lane < 6) ? datanorm[lane] : 0.f;

    const float ninf = __int_as_float(0xff800000);
    float accs = 0.f, accq = 0.f;

    for (int n = gw; n < N; n += nw) {
        int2 cat = __ldg((const int2*)x_cat + n);
        int p = cat.x < 0 ? -cat.x : cat.x;
        int pi = (p == 1) ? 0 : (p == 2) ? 1 : (p == 11) ? 2 : (p == 13) ? 3
               : (p == 22) ? 4 : (p == 130) ? 5 : 6;

        float xi = (lane < 6) ? x_cont[n * 6 + lane] * dnr : 0.f;
        float c0 = (lane < 8)  ? emb_charge[(cat.y + 1) * 8 + lane]
                 : (lane < 16) ? emb_pdg[pi * 8 + lane - 8] : 0.f;

        float acat = bcat;
        #pragma unroll
        for (int j = 0; j < 16; j++)
            acat += __shfl_sync(0xffffffffu, c0, j) * wcat[j];
        float acont = bcont;
        #pragma unroll
        for (int j = 0; j < 6; j++)
            acont += __shfl_sync(0xffffffffu, xi, j) * wcont[j];

        float in = eluf(lane < 16 ? acat : acont);

        float a = benc;
        #pragma unroll
        for (int j = 0; j < 32; j++)
            a += __shfl_sync(0xffffffffu, in, j) * wenc[j];
        float h = eluf(a);

        g_emb[(long long)n * 32 + lane] = h;
        g_max[(long long)n * 32 + lane] = ninf;
        accs += h;
        accq += h * h;
    }
    flush_stats(accs, accq, 0);
}

// ---------------- K2: apply BN1, compute u,v (warp/node) ----------------
__global__ void k_prep(const float* __restrict__ g_all, const float* __restrict__ be_all,
                       const float* __restrict__ W_msg, int N)
{
    int lane = threadIdx.x & 31;
    int gw   = (blockIdx.x * blockDim.x + threadIdx.x) >> 5;
    int nw   = (gridDim.x * blockDim.x) >> 5;

    float wd[32], wb[32];
    #pragma unroll
    for (int j = 0; j < 32; j++) {
        float a = W_msg[j * 32 + lane];
        float b = W_msg[1024 + j * 32 + lane];
        wd[j] = a - b;
        wb[j] = b;
    }
    double m   = g_sums[lane] / (double)N;
    double var = g_sums[32 + lane] / (double)N - m * m;
    float inv  = rsqrtf((float)var + BN_EPS);
    float ga   = g_all[lane];
    float scale = ga * inv;
    float shift = be_all[lane] - (float)m * ga * inv;

    for (int n = gw; n < N; n += nw) {
        float x = g_emb[(long long)n * 32 + lane] * scale + shift;
        g_emb[(long long)n * 32 + lane] = x;
        float au = 0.f, av = 0.f;
        #pragma unroll
        for (int j = 0; j < 32; j++) {
            float ej = __shfl_sync(0xffffffffu, x, j);
            au += ej * wd[j];
            av += ej * wb[j];
        }
        g_u[(long long)n * 32 + lane] = au;
        g_v[(long long)n * 32 + lane] = av;
    }
}

// ---------------- K3: edge atomic max (float4, 2 edges/thread) ----------------
__device__ __forceinline__ void amax1(float* a, float v, float c) {
    if (v > c) {
        if (__float_as_int(v) >= 0) atomicMax((int*)a, __float_as_int(v));
        else                        atomicMin((unsigned int*)a, __float_as_uint(v));
    }
}

__global__ void k_edge(const int* __restrict__ ei, int E, int EH)
{
    int tid = blockIdx.x * blockDim.x + threadIdx.x;
    int c = tid & 7;
    int e0 = tid >> 3;
    if (e0 >= EH) return;
    int e1 = e0 + EH;
    bool has1 = (e1 < E);

    int s0 = __ldg(&ei[e0]);
    int d0 = __ldg(&ei[E + e0]);
    int s1 = has1 ? __ldg(&ei[e1])     : s0;
    int d1 = has1 ? __ldg(&ei[E + e1]) : d0;

    const float4* v4 = (const float4*)g_v;
    float4* m4 = (float4*)g_max;

    float4 val0 = __ldg(&v4[(long long)s0 * 8 + c]);
    float4 val1 = __ldg(&v4[(long long)s1 * 8 + c]);
    float4 cur0 = m4[(long long)d0 * 8 + c];
    float4 cur1 = m4[(long long)d1 * 8 + c];

    float* a0 = &g_max[(long long)d0 * 32 + c * 4];
    amax1(a0 + 0, val0.x, cur0.x);
    amax1(a0 + 1, val0.y, cur0.y);
    amax1(a0 + 2, val0.z, cur0.z);
    amax1(a0 + 3, val0.w, cur0.w);
    if (has1) {
        float* a1 = &g_max[(long long)d1 * 32 + c * 4];
        amax1(a1 + 0, val1.x, cur1.x);
        amax1(a1 + 1, val1.y, cur1.y);
        amax1(a1 + 2, val1.z, cur1.z);
        amax1(a1 + 3, val1.w, cur1.w);
    }
}

// ---------------- K4: finalize agg + BN2 stats (warp/node) ----------------
__global__ void k_agg(const float* __restrict__ b_msg, int N)
{
    int lane = threadIdx.x & 31;
    int gw   = (blockIdx.x * blockDim.x + threadIdx.x) >> 5;
    int nw   = (gridDim.x * blockDim.x) >> 5;
    float bmr = b_msg[lane];
    float accs = 0.f, accq = 0.f;

    for (int n = gw; n < N; n += nw) {
        float mval = g_max[(long long)n * 32 + lane];
        float uval = g_u[(long long)n * 32 + lane];
        int m0 = __shfl_sync(0xffffffffu, __float_as_int(mval), 0);
        bool empty = (m0 == (int)0xff800000);
        float x = empty ? 0.f : (uval + bmr + mval);
        g_v[(long long)n * 32 + lane] = x;
        accs += x;
        accq += x * x;
    }
    flush_stats(accs, accq, 64);
}

// ---------------- K5: residual + output MLP (warp/node) ----------------
__global__ void k_out(const float* __restrict__ g_conv, const float* __restrict__ be_conv,
                      const float* __restrict__ W_o1, const float* __restrict__ b_o1,
                      const float* __restrict__ W_o2, const float* __restrict__ b_o2,
                      float* __restrict__ out, int N)
{
    int lane = threadIdx.x & 31;
    int gw   = (blockIdx.x * blockDim.x + threadIdx.x) >> 5;
    int nw   = (gridDim.x * blockDim.x) >> 5;
    int l16  = lane & 15;

    float w1[32];
    #pragma unroll
    for (int j = 0; j < 32; j++) w1[j] = W_o1[j * 16 + l16];
    float w2 = W_o2[l16];
    float b1 = b_o1[l16];
    float b2 = b_o2[0];

    double m   = g_sums[64 + lane] / (double)N;
    double var = g_sums[96 + lane] / (double)N - m * m;
    float inv  = rsqrtf((float)var + BN_EPS);
    float gc   = g_conv[lane];
    float scale = gc * inv;
    float shift = be_conv[lane] - (float)m * gc * inv;

    for (int n = gw; n < N; n += nw) {
        float h = g_emb[(long long)n * 32 + lane]
                + g_v[(long long)n * 32 + lane] * scale + shift;
        float a = b1;
        #pragma unroll
        for (int j = 0; j < 32; j++)
            a += __shfl_sync(0xffffffffu, h, j) * w1[j];
        float o1 = eluf(a);
        float mm = o1 * w2;
        mm += __shfl_xor_sync(0xffffffffu, mm, 1);
        mm += __shfl_xor_sync(0xffffffffu, mm, 2);
        mm += __shfl_xor_sync(0xffffffffu, mm, 4);
        mm += __shfl_xor_sync(0xffffffffu, mm, 8);
        if (lane == 0) out[n] = mm + b2;
    }
}

extern "C" void kernel_launch(void* const* d_in, const int* in_sizes, int n_in,
                              void* d_out, int out_size)
{
    const float* x_cont     = (const float*)d_in[0];
    const int*   x_cat      = (const int*)  d_in[1];
    const int*   edge_index = (const int*)  d_in[2];
    const float* datanorm   = (const float*)d_in[4];
    const float* W_cont     = (const float*)d_in[5];
    const float* b_cont     = (const float*)d_in[6];
    const float* emb_charge = (const float*)d_in[7];
    const float* emb_pdg    = (const float*)d_in[8];
    const float* W_cat      = (const float*)d_in[9];
    const float* b_cat      = (const float*)d_in[10];
    const float* W_enc      = (const float*)d_in[11];
    const float* b_enc      = (const float*)d_in[12];
    const float* g_all      = (const float*)d_in[13];
    const float* be_all     = (const float*)d_in[14];
    const float* W_msg      = (const float*)d_in[15];
    const float* b_msg      = (const float*)d_in[16];
    const float* g_conv     = (const float*)d_in[17];
    const float* be_conv    = (const float*)d_in[18];
    const float* W_o1       = (const float*)d_in[19];
    const float* b_o1       = (const float*)d_in[20];
    const float* W_o2       = (const float*)d_in[21];
    const float* b_o2       = (const float*)d_in[22];
    float* out = (float*)d_out;

    int N = in_sizes[0] / 6;
    int E = in_sizes[2] / 2;

    // warp-per-node kernels: 256 threads (8 warps) x 512 blocks (~24 nodes/warp)
    const int TB = 256;
    const int NB = 512;

    k_zero<<<1, 128>>>();
    k_encode<<<NB, TB>>>(x_cont, x_cat, datanorm, W_cont, b_cont,
                         emb_charge, emb_pdg, W_cat, b_cat, W_enc, b_enc, N);
    k_prep<<<NB, TB>>>(g_all, be_all, W_msg, N);
    int EH = (E + 1) / 2;
    long long tot = (long long)EH * 8;
    int eb = (int)((tot + 255) / 256);
    k_edge<<<eb, 256>>>(edge_index, E, EH);
    k_agg<<<NB, TB>>>(b_msg, N);
    k_out<<<NB, TB>>>(g_conv, be_conv, W_o1, b_o1, W_o2, b_o2, out, N);
}